// round 6
// baseline (speedup 1.0000x reference)
#include <cuda_runtime.h>
#include <math.h>

#define D_MODEL 256
#define STATE_N 64
#define SEQ_L   8192
#define HALF_L  4096

// Scratch: K_hat[d, L] complex64 (16 MB) as a device global (no runtime alloc).
__device__ float2 g_Khat[D_MODEL * SEQ_L];

// ---------------------------------------------------------------------------
// Kernel 1: Cauchy + Woodbury with the g-purely-imaginary fast path.
//   g = (2/dt)(1-z)/(1+z) = i * (2/dt) tan(theta/2)  (exact on |z|=1)
//   => dr = -lam_re = softplus (per-n constant), fold dr into weights.
//   Inner loop: 11 fma-pipe ops + 1 MUFU per (k,n).
// k == L/2 (eps-clamped, g has a huge REAL part) takes an exact general path.
// ---------------------------------------------------------------------------
__global__ void __launch_bounds__(256) cauchy_kernel(
    const float* __restrict__ Lam_re, const float* __restrict__ Lam_im,
    const float* __restrict__ P_re,   const float* __restrict__ P_im,
    const float* __restrict__ B_re,   const float* __restrict__ B_im,
    const float* __restrict__ log_dt)
{
    __shared__ float4 s_p1[STATE_N];  // (lam_im, sp*sp, w1r, w1i)
    __shared__ float4 s_p2[STATE_N];  // (w1r*sp, w1i*sp, pp*sp, bb*sp)
    __shared__ float4 s_p3[STATE_N];  // (pp, bb, sp, 0)
    __shared__ float  s_scal;

    const int d   = blockIdx.y;
    const int tid = threadIdx.x;

    if (tid < STATE_N) {
        const int idx = d * STATE_N + tid;
        float lr = Lam_re[idx];
        float li = Lam_im[idx];
        float sp = fmaxf(lr, 0.0f) + log1pf(expf(-fabsf(lr)));  // softplus = -lam_re
        float pr = P_re[idx], pi = P_im[idx];
        float br = B_re[idx], bi = B_im[idx];
        float w1r = pr * br + pi * bi;    // conj(P)*B
        float w1i = pr * bi - pi * br;
        float pp  = pr * pr + pi * pi;
        float bb  = br * br + bi * bi;
        s_p1[tid] = make_float4(li, sp * sp, w1r, w1i);
        s_p2[tid] = make_float4(w1r * sp, w1i * sp, pp * sp, bb * sp);
        s_p3[tid] = make_float4(pp, bb, sp, 0.0f);
    }
    if (tid == 0) s_scal = 2.0f * expf(-log_dt[d]);   // 2/dt
    __syncthreads();

    const int k = blockIdx.x * blockDim.x + tid;
    const float scal = s_scal;

    // z = exp(-2*pi*i*k/L), f32 angle as in the reference.
    const float w0 = (float)(-6.283185307179586476925286766559 / (double)SEQ_L);
    float zs, zc;
    sincosf(w0 * (float)k, &zs, &zc);

    float dzr = 1.0f + zc;
    float dzi = zs;
    if (k == HALF_L) { dzr = 1.1920929e-7f; dzi = 0.0f; }   // reference eps clamp
    float idm = 1.0f / (dzr * dzr + dzi * dzi);

    float nr = 1.0f - zc;
    float ni = -zs;
    float gi  = scal * (ni * dzr - nr * dzi) * idm;   // Im(g)
    float pfr =  2.0f * dzr * idm;                    // pref = 2/(1+z)
    float pfi = -2.0f * dzi * idm;

    float PRBr, PRBi, BRPr, BRPi, PRPr, PRPi, BRBr, BRBi;

    if (k != HALF_L) {
        // ---- fast path: g treated as purely imaginary ----
        float SA = 0.f, SB = 0.f, SC = 0.f, SD = 0.f;   // sums of w'*inv
        float TA = 0.f, TB = 0.f, TC = 0.f, TD = 0.f;   // sums of w*Ri
#pragma unroll 8
        for (int n = 0; n < STATE_N; n++) {
            float4 a = s_p1[n];
            float4 b = s_p2[n];
            float4 c = s_p3[n];
            float di = gi - a.x;                  // Im(g - lam)
            float m  = fmaf(di, di, a.y);         // |g-lam|^2 = di^2 + sp^2
            float inv; asm("rcp.approx.f32 %0, %1;" : "=f"(inv) : "f"(m));
            float Ri = di * inv;
            SA = fmaf(b.x, inv, SA);
            SB = fmaf(b.y, inv, SB);
            SC = fmaf(b.z, inv, SC);
            SD = fmaf(b.w, inv, SD);
            TA = fmaf(a.z, Ri, TA);
            TB = fmaf(a.w, Ri, TB);
            TC = fmaf(c.x, Ri, TC);
            TD = fmaf(c.y, Ri, TD);
        }
        // R_true = (sp*inv, -Ri); assemble the four complex sums
        PRBr = SA + TB;  PRBi = SB - TA;
        BRPr = SA - TB;  BRPi = -SB - TA;
        PRPr = SC;       PRPi = -TC;
        BRBr = SD;       BRBi = -TD;
    } else {
        // ---- exact path for the eps-clamped point (g real part dominant) ----
        float gr = scal * (nr * dzr + ni * dzi) * idm;
        PRBr = PRBi = BRPr = BRPi = PRPr = PRPi = BRBr = BRBi = 0.f;
        for (int n = 0; n < STATE_N; n++) {
            float4 a = s_p1[n];
            float4 c = s_p3[n];
            float dr = gr + c.z;                  // gr - lam_re = gr + sp
            float di = gi - a.x;
            float m  = fmaf(dr, dr, di * di);
            float inv = 1.0f / m;
            float Rtr = dr * inv;
            float Rti = -di * inv;
            float w1r = a.z, w1i = a.w, pp = c.x, bb = c.y;
            PRBr += w1r * Rtr - w1i * Rti;
            PRBi += w1r * Rti + w1i * Rtr;
            BRPr += w1r * Rtr + w1i * Rti;
            BRPi += w1r * Rti - w1i * Rtr;
            PRPr += pp * Rtr;  PRPi += pp * Rti;
            BRBr += bb * Rtr;  BRBi += bb * Rti;
        }
    }

    // Woodbury: K_hat = pref * (BRB - BRP*PRB/(1+PRP))
    float qr = 1.0f + PRPr, qi = PRPi;
    float iq = 1.0f / (qr * qr + qi * qi);
    float numr = BRPr * PRBr - BRPi * PRBi;
    float numi = BRPr * PRBi + BRPi * PRBr;
    float tr = (numr * qr + numi * qi) * iq;
    float ti = (numi * qr - numr * qi) * iq;
    float hr = BRBr - tr;
    float hi = BRBi - ti;

    g_Khat[d * SEQ_L + k] = make_float2(pfr * hr - pfi * hi,
                                        pfr * hi + pfi * hr);
}

// ---------------------------------------------------------------------------
// Kernel 2: Re(ifft_L(X)) = Hermitian fold + 4096-pt radix-4 inverse Stockham.
// One CTA per d-row, 64 KB smem ping-pong, 1024 threads.
// ---------------------------------------------------------------------------
__global__ void __launch_bounds__(1024) ifft_kernel(float* __restrict__ out)
{
    extern __shared__ float2 sm[];
    float2* x = sm;              // buffer A
    float2* y = sm + HALF_L;     // buffer B

    const int d   = blockIdx.x;
    const int tid = threadIdx.x;
    const int NT  = 1024;

    const float2* src = g_Khat + d * SEQ_L;

    // Hermitian fold + even/odd pack:  x[k] = E[k] + i*O[k]
    const float thL = 6.28318530717958647692f / (float)SEQ_L;
    for (int kk = tid; kk < HALF_L; kk += NT) {
        float2 Xa  = src[kk];
        float2 Xam = src[kk == 0 ? 0 : SEQ_L - kk];
        float2 Xb  = src[kk + HALF_L];
        float2 Xbm = src[HALF_L - kk];
        float Ar = 0.5f * (Xa.x + Xam.x), Ai = 0.5f * (Xa.y - Xam.y);
        float Br = 0.5f * (Xb.x + Xbm.x), Bi = 0.5f * (Xb.y - Xbm.y);
        float Er = 0.5f * (Ar + Br), Ei = 0.5f * (Ai + Bi);
        float Dr = 0.5f * (Ar - Br), Di = 0.5f * (Ai - Bi);
        float swr, swi;
        __sincosf(thL * (float)kk, &swi, &swr);
        float Or = Dr * swr - Di * swi;
        float Oi = Dr * swi + Di * swr;
        x[kk] = make_float2(Er - Oi, Ei + Or);
    }
    __syncthreads();

    // 6 radix-4 inverse Stockham stages (4096 = 4^6), e^{+} twiddles
    int n = HALF_L, s = 1, ls = 0;
    while (n > 1) {
        const int m = n >> 2;
        const float th = 6.28318530717958647692f / (float)n;
        for (int u = tid; u < (HALF_L >> 2); u += NT) {
            int p = u >> ls;
            int q = u & (s - 1);
            int base = q + s * p;
            float2 a  = x[base];
            float2 b  = x[base + s * m];
            float2 c  = x[base + s * 2 * m];
            float2 dd = x[base + s * 3 * m];

            float w1i, w1r;
            __sincosf(th * (float)p, &w1i, &w1r);        // w = e^{+i th p}
            float w2r = w1r * w1r - w1i * w1i;           // w^2
            float w2i = 2.0f * w1r * w1i;
            float w3r = w2r * w1r - w2i * w1i;           // w^3
            float w3i = w2r * w1i + w2i * w1r;

            float acr = a.x + c.x, aci = a.y + c.y;
            float amr = a.x - c.x, ami = a.y - c.y;
            float bdr = b.x + dd.x, bdi = b.y + dd.y;
            float bmr = b.x - dd.x, bmi = b.y - dd.y;

            float X0r = acr + bdr, X0i = aci + bdi;
            float X2r = acr - bdr, X2i = aci - bdi;
            float X1r = amr - bmi, X1i = ami + bmr;
            float X3r = amr + bmi, X3i = ami - bmr;

            int ob = q + s * 4 * p;
            y[ob]         = make_float2(X0r, X0i);
            y[ob + s]     = make_float2(X1r * w1r - X1i * w1i,
                                        X1r * w1i + X1i * w1r);
            y[ob + 2 * s] = make_float2(X2r * w2r - X2i * w2i,
                                        X2r * w2i + X2i * w2r);
            y[ob + 3 * s] = make_float2(X3r * w3r - X3i * w3i,
                                        X3r * w3i + X3i * w3r);
        }
        __syncthreads();
        float2* tmp = x; x = y; y = tmp;
        n = m; s <<= 2; ls += 2;
    }

    // x[m] = K[2m] + i*K[2m+1]  ->  interleaved real output
    const float scale = 1.0f / (float)HALF_L;
    float* dst = out + d * SEQ_L;
    for (int mI = tid; mI < HALF_L; mI += NT) {
        float2 v = x[mI];
        dst[2 * mI]     = v.x * scale;
        dst[2 * mI + 1] = v.y * scale;
    }
}

// ---------------------------------------------------------------------------
extern "C" void kernel_launch(void* const* d_in, const int* in_sizes, int n_in,
                              void* d_out, int out_size)
{
    const float* Lam_re = (const float*)d_in[0];
    const float* Lam_im = (const float*)d_in[1];
    const float* P_re   = (const float*)d_in[2];
    const float* P_im   = (const float*)d_in[3];
    const float* B_re   = (const float*)d_in[4];
    const float* B_im   = (const float*)d_in[5];
    const float* log_dt = (const float*)d_in[6];

    float* out = (float*)d_out;

    // Stage 1: Cauchy + Woodbury -> K_hat
    dim3 gridA(SEQ_L / 256, D_MODEL);   // 32 x 256
    cauchy_kernel<<<gridA, 256>>>(Lam_re, Lam_im, P_re, P_im, B_re, B_im, log_dt);

    // Stage 2: Hermitian fold + radix-4 half-length iFFT per row -> K
    cudaFuncSetAttribute(ifft_kernel,
                         cudaFuncAttributeMaxDynamicSharedMemorySize, 65536);
    ifft_kernel<<<D_MODEL, 1024, 65536>>>(out);

    // Tail of the output: D buffer (zeros in the reference)
    long kElems = (long)D_MODEL * SEQ_L;
    if ((long)out_size > kElems) {
        cudaMemsetAsync(out + kElems, 0,
                        ((long)out_size - kElems) * sizeof(float), 0);
    }
}

// round 7
// speedup vs baseline: 1.0168x; 1.0168x over previous
#include <cuda_runtime.h>
#include <math.h>

#define D_MODEL 256
#define STATE_N 64
#define SEQ_L   8192
#define HALF_L  4096

// Scratch: K_hat[d, L] complex64 (16 MB) as a device global (no runtime alloc).
__device__ float2 g_Khat[D_MODEL * SEQ_L];

// ---------------------------------------------------------------------------
// Kernel 1: Cauchy + Woodbury, 2 k-points per thread (k and k+L/2).
// g is purely imaginary on |z|=1 (validated R6, rel_err 1.3e-6):
//   per point per n: di, m=fma(di,di,sp2), rcp, Ri=di*inv, 8 accum FMAs.
// 3 shared loads amortized over 2 points.
// ---------------------------------------------------------------------------
__global__ void __launch_bounds__(256) cauchy_kernel(
    const float* __restrict__ Lam_re, const float* __restrict__ Lam_im,
    const float* __restrict__ P_re,   const float* __restrict__ P_im,
    const float* __restrict__ B_re,   const float* __restrict__ B_im,
    const float* __restrict__ log_dt)
{
    __shared__ float4 s_p1[STATE_N];  // (lam_im, sp*sp, w1r, w1i)
    __shared__ float4 s_p2[STATE_N];  // (w1r*sp, w1i*sp, pp*sp, bb*sp)
    __shared__ float4 s_p3[STATE_N];  // (pp, bb, sp, 0)
    __shared__ float  s_scal;

    const int d   = blockIdx.y;
    const int tid = threadIdx.x;

    if (tid < STATE_N) {
        const int idx = d * STATE_N + tid;
        float lr = Lam_re[idx];
        float li = Lam_im[idx];
        float sp = fmaxf(lr, 0.0f) + log1pf(expf(-fabsf(lr)));  // softplus = -lam_re
        float pr = P_re[idx], pi = P_im[idx];
        float br = B_re[idx], bi = B_im[idx];
        float w1r = pr * br + pi * bi;    // conj(P)*B
        float w1i = pr * bi - pi * br;
        float pp  = pr * pr + pi * pi;
        float bb  = br * br + bi * bi;
        s_p1[tid] = make_float4(li, sp * sp, w1r, w1i);
        s_p2[tid] = make_float4(w1r * sp, w1i * sp, pp * sp, bb * sp);
        s_p3[tid] = make_float4(pp, bb, sp, 0.0f);
    }
    if (tid == 0) s_scal = 2.0f * expf(-log_dt[d]);   // 2/dt
    __syncthreads();

    const int k1 = blockIdx.x * blockDim.x + tid;     // 0..4095
    const int k2 = k1 + HALF_L;                       // 4096..8191
    const float scal = s_scal;

    // per-point prologue (f32 angle as in the reference)
    const float w0 = (float)(-6.283185307179586476925286766559 / (double)SEQ_L);
    float zs1, zc1, zs2, zc2;
    sincosf(w0 * (float)k1, &zs1, &zc1);
    sincosf(w0 * (float)k2, &zs2, &zc2);

    float dzr1 = 1.0f + zc1, dzi1 = zs1;
    float dzr2 = 1.0f + zc2, dzi2 = zs2;
    if (k2 == HALF_L) { dzr2 = 1.1920929e-7f; dzi2 = 0.0f; }
    float idm1 = 1.0f / (dzr1 * dzr1 + dzi1 * dzi1);
    float idm2 = 1.0f / (dzr2 * dzr2 + dzi2 * dzi2);

    float nr1 = 1.0f - zc1, ni1 = -zs1;
    float nr2 = 1.0f - zc2, ni2 = -zs2;
    const float gi1  = scal * (ni1 * dzr1 - nr1 * dzi1) * idm1;
    const float gi2  = scal * (ni2 * dzr2 - nr2 * dzi2) * idm2;
    float pfr1 =  2.0f * dzr1 * idm1, pfi1 = -2.0f * dzi1 * idm1;
    float pfr2 =  2.0f * dzr2 * idm2, pfi2 = -2.0f * dzi2 * idm2;

    float SA1 = 0.f, SB1 = 0.f, SC1 = 0.f, SD1 = 0.f;
    float TA1 = 0.f, TB1 = 0.f, TC1 = 0.f, TD1 = 0.f;
    float SA2 = 0.f, SB2 = 0.f, SC2 = 0.f, SD2 = 0.f;
    float TA2 = 0.f, TB2 = 0.f, TC2 = 0.f, TD2 = 0.f;

#pragma unroll 4
    for (int n = 0; n < STATE_N; n++) {
        float4 a = s_p1[n];
        float4 b = s_p2[n];
        float4 c = s_p3[n];
        // point 1
        float di1 = gi1 - a.x;
        float m1  = fmaf(di1, di1, a.y);
        float i1; asm("rcp.approx.f32 %0, %1;" : "=f"(i1) : "f"(m1));
        float Ri1 = di1 * i1;
        SA1 = fmaf(b.x, i1, SA1);  SB1 = fmaf(b.y, i1, SB1);
        SC1 = fmaf(b.z, i1, SC1);  SD1 = fmaf(b.w, i1, SD1);
        TA1 = fmaf(a.z, Ri1, TA1); TB1 = fmaf(a.w, Ri1, TB1);
        TC1 = fmaf(c.x, Ri1, TC1); TD1 = fmaf(c.y, Ri1, TD1);
        // point 2
        float di2 = gi2 - a.x;
        float m2  = fmaf(di2, di2, a.y);
        float i2; asm("rcp.approx.f32 %0, %1;" : "=f"(i2) : "f"(m2));
        float Ri2 = di2 * i2;
        SA2 = fmaf(b.x, i2, SA2);  SB2 = fmaf(b.y, i2, SB2);
        SC2 = fmaf(b.z, i2, SC2);  SD2 = fmaf(b.w, i2, SD2);
        TA2 = fmaf(a.z, Ri2, TA2); TB2 = fmaf(a.w, Ri2, TB2);
        TC2 = fmaf(c.x, Ri2, TC2); TD2 = fmaf(c.y, Ri2, TD2);
    }

    // ---- finalize both points ----
    float2* dst = g_Khat + d * SEQ_L;
#pragma unroll
    for (int pt = 0; pt < 2; pt++) {
        float SA = pt ? SA2 : SA1, SB = pt ? SB2 : SB1;
        float SC = pt ? SC2 : SC1, SD = pt ? SD2 : SD1;
        float TA = pt ? TA2 : TA1, TB = pt ? TB2 : TB1;
        float TC = pt ? TC2 : TC1, TD = pt ? TD2 : TD1;
        float pfr = pt ? pfr2 : pfr1, pfi = pt ? pfi2 : pfi1;
        int   k   = pt ? k2 : k1;

        float PRBr, PRBi, BRPr, BRPi, PRPr, PRPi, BRBr, BRBi;
        if (k != HALF_L) {
            PRBr = SA + TB;  PRBi = SB - TA;
            BRPr = SA - TB;  BRPi = -SB - TA;
            PRPr = SC;       PRPi = -TC;
            BRBr = SD;       BRBi = -TD;
        } else {
            // exact general path for the eps-clamped point (g real part huge)
            float gi = gi2;
            float gr = scal * (nr2 * dzr2 + ni2 * dzi2) * idm2;
            PRBr = PRBi = BRPr = BRPi = PRPr = PRPi = BRBr = BRBi = 0.f;
            for (int n = 0; n < STATE_N; n++) {
                float4 a = s_p1[n];
                float4 c = s_p3[n];
                float dr = gr + c.z;              // gr - lam_re
                float di = gi - a.x;
                float m  = fmaf(dr, dr, di * di);
                float inv = 1.0f / m;
                float Rtr = dr * inv;
                float Rti = -di * inv;
                float w1r = a.z, w1i = a.w, pp = c.x, bb = c.y;
                PRBr += w1r * Rtr - w1i * Rti;
                PRBi += w1r * Rti + w1i * Rtr;
                BRPr += w1r * Rtr + w1i * Rti;
                BRPi += w1r * Rti - w1i * Rtr;
                PRPr += pp * Rtr;  PRPi += pp * Rti;
                BRBr += bb * Rtr;  BRBi += bb * Rti;
            }
        }

        float qr = 1.0f + PRPr, qi = PRPi;
        float iq = 1.0f / (qr * qr + qi * qi);
        float numr = BRPr * PRBr - BRPi * PRBi;
        float numi = BRPr * PRBi + BRPi * PRBr;
        float tr = (numr * qr + numi * qi) * iq;
        float ti = (numi * qr - numr * qi) * iq;
        float hr = BRBr - tr;
        float hi = BRBi - ti;
        dst[k] = make_float2(pfr * hr - pfi * hi, pfr * hi + pfi * hr);
    }
}

// ---------------------------------------------------------------------------
// Empty diagnostic kernels: shift the ncu skip-window so launch #6 = cauchy.
// ---------------------------------------------------------------------------
__global__ void dummy_a() {}
__global__ void dummy_b() {}
__global__ void dummy_c() {}

// ---------------------------------------------------------------------------
// Kernel 2: Re(ifft_L(X)) = Hermitian fold + 4096-pt radix-4 inverse Stockham.
// One CTA per d-row, 64 KB smem ping-pong, 1024 threads.
// ---------------------------------------------------------------------------
__global__ void __launch_bounds__(1024) ifft_kernel(float* __restrict__ out)
{
    extern __shared__ float2 sm[];
    float2* x = sm;
    float2* y = sm + HALF_L;

    const int d   = blockIdx.x;
    const int tid = threadIdx.x;
    const int NT  = 1024;

    const float2* src = g_Khat + d * SEQ_L;

    // Hermitian fold + even/odd pack:  x[k] = E[k] + i*O[k]
    const float thL = 6.28318530717958647692f / (float)SEQ_L;
    for (int kk = tid; kk < HALF_L; kk += NT) {
        float2 Xa  = src[kk];
        float2 Xam = src[kk == 0 ? 0 : SEQ_L - kk];
        float2 Xb  = src[kk + HALF_L];
        float2 Xbm = src[HALF_L - kk];
        float Ar = 0.5f * (Xa.x + Xam.x), Ai = 0.5f * (Xa.y - Xam.y);
        float Br = 0.5f * (Xb.x + Xbm.x), Bi = 0.5f * (Xb.y - Xbm.y);
        float Er = 0.5f * (Ar + Br), Ei = 0.5f * (Ai + Bi);
        float Dr = 0.5f * (Ar - Br), Di = 0.5f * (Ai - Bi);
        float swr, swi;
        __sincosf(thL * (float)kk, &swi, &swr);
        float Or = Dr * swr - Di * swi;
        float Oi = Dr * swi + Di * swr;
        x[kk] = make_float2(Er - Oi, Ei + Or);
    }
    __syncthreads();

    int n = HALF_L, s = 1, ls = 0;
    while (n > 1) {
        const int m = n >> 2;
        const float th = 6.28318530717958647692f / (float)n;
        for (int u = tid; u < (HALF_L >> 2); u += NT) {
            int p = u >> ls;
            int q = u & (s - 1);
            int base = q + s * p;
            float2 a  = x[base];
            float2 b  = x[base + s * m];
            float2 c  = x[base + s * 2 * m];
            float2 dd = x[base + s * 3 * m];

            float w1i, w1r;
            __sincosf(th * (float)p, &w1i, &w1r);
            float w2r = w1r * w1r - w1i * w1i;
            float w2i = 2.0f * w1r * w1i;
            float w3r = w2r * w1r - w2i * w1i;
            float w3i = w2r * w1i + w2i * w1r;

            float acr = a.x + c.x, aci = a.y + c.y;
            float amr = a.x - c.x, ami = a.y - c.y;
            float bdr = b.x + dd.x, bdi = b.y + dd.y;
            float bmr = b.x - dd.x, bmi = b.y - dd.y;

            float X0r = acr + bdr, X0i = aci + bdi;
            float X2r = acr - bdr, X2i = aci - bdi;
            float X1r = amr - bmi, X1i = ami + bmr;
            float X3r = amr + bmi, X3i = ami - bmr;

            int ob = q + s * 4 * p;
            y[ob]         = make_float2(X0r, X0i);
            y[ob + s]     = make_float2(X1r * w1r - X1i * w1i,
                                        X1r * w1i + X1i * w1r);
            y[ob + 2 * s] = make_float2(X2r * w2r - X2i * w2i,
                                        X2r * w2i + X2i * w2r);
            y[ob + 3 * s] = make_float2(X3r * w3r - X3i * w3i,
                                        X3r * w3i + X3i * w3r);
        }
        __syncthreads();
        float2* tmp = x; x = y; y = tmp;
        n = m; s <<= 2; ls += 2;
    }

    const float scale = 1.0f / (float)HALF_L;
    float* dst = out + d * SEQ_L;
    for (int mI = tid; mI < HALF_L; mI += NT) {
        float2 v = x[mI];
        dst[2 * mI]     = v.x * scale;
        dst[2 * mI + 1] = v.y * scale;
    }
}

// ---------------------------------------------------------------------------
extern "C" void kernel_launch(void* const* d_in, const int* in_sizes, int n_in,
                              void* d_out, int out_size)
{
    const float* Lam_re = (const float*)d_in[0];
    const float* Lam_im = (const float*)d_in[1];
    const float* P_re   = (const float*)d_in[2];
    const float* P_im   = (const float*)d_in[3];
    const float* B_re   = (const float*)d_in[4];
    const float* B_im   = (const float*)d_in[5];
    const float* log_dt = (const float*)d_in[6];

    float* out = (float*)d_out;

    // Stage 1: Cauchy + Woodbury -> K_hat (2 points per thread)
    dim3 gridA(HALF_L / 256, D_MODEL);   // 16 x 256
    cauchy_kernel<<<gridA, 256>>>(Lam_re, Lam_im, P_re, P_im, B_re, B_im, log_dt);

    // Diagnostic no-ops: make ncu's skip-5 window land on cauchy next round.
    dummy_a<<<1, 32>>>();
    dummy_b<<<1, 32>>>();
    dummy_c<<<1, 32>>>();

    // Stage 2: Hermitian fold + radix-4 half-length iFFT per row -> K
    cudaFuncSetAttribute(ifft_kernel,
                         cudaFuncAttributeMaxDynamicSharedMemorySize, 65536);
    ifft_kernel<<<D_MODEL, 1024, 65536>>>(out);

    // Tail of the output: D buffer (zeros in the reference)
    long kElems = (long)D_MODEL * SEQ_L;
    if ((long)out_size > kElems) {
        cudaMemsetAsync(out + kElems, 0,
                        ((long)out_size - kElems) * sizeof(float), 0);
    }
}

// round 8
// speedup vs baseline: 1.0355x; 1.0183x over previous
#include <cuda_runtime.h>
#include <math.h>

#define D_MODEL 256
#define STATE_N 64
#define SEQ_L   8192
#define HALF_L  4096

// Scratch: K_hat[d, L] complex64 (16 MB) as a device global (no runtime alloc).
__device__ float2 g_Khat[D_MODEL * SEQ_L];

// ---------------------------------------------------------------------------
// Empty kernels: position cauchy_kernel into ncu's profiled slot (launch #4).
// ---------------------------------------------------------------------------
__global__ void dummy_a() {}
__global__ void dummy_b() {}
__global__ void dummy_c() {}

// ---------------------------------------------------------------------------
// Kernel 1: Cauchy + Woodbury, 2 k-points per thread (k and k+L/2).
// g is purely imaginary on |z|=1 (validated R6, rel_err 1.3e-6):
//   per point per n: di, m=fma(di,di,sp2), rcp, Ri=di*inv, 8 accum FMAs.
// ---------------------------------------------------------------------------
__global__ void __launch_bounds__(256) cauchy_kernel(
    const float* __restrict__ Lam_re, const float* __restrict__ Lam_im,
    const float* __restrict__ P_re,   const float* __restrict__ P_im,
    const float* __restrict__ B_re,   const float* __restrict__ B_im,
    const float* __restrict__ log_dt)
{
    __shared__ float4 s_p1[STATE_N];  // (lam_im, sp*sp, w1r, w1i)
    __shared__ float4 s_p2[STATE_N];  // (w1r*sp, w1i*sp, pp*sp, bb*sp)
    __shared__ float2 s_p3[STATE_N];  // (pp, bb)
    __shared__ float  s_sp[STATE_N];  // sp (cold: exact path only)
    __shared__ float  s_scal;

    const int d   = blockIdx.y;
    const int tid = threadIdx.x;

    if (tid < STATE_N) {
        const int idx = d * STATE_N + tid;
        float lr = Lam_re[idx];
        float li = Lam_im[idx];
        float sp = fmaxf(lr, 0.0f) + log1pf(expf(-fabsf(lr)));  // softplus = -lam_re
        float pr = P_re[idx], pi = P_im[idx];
        float br = B_re[idx], bi = B_im[idx];
        float w1r = pr * br + pi * bi;    // conj(P)*B
        float w1i = pr * bi - pi * br;
        float pp  = pr * pr + pi * pi;
        float bb  = br * br + bi * bi;
        s_p1[tid] = make_float4(li, sp * sp, w1r, w1i);
        s_p2[tid] = make_float4(w1r * sp, w1i * sp, pp * sp, bb * sp);
        s_p3[tid] = make_float2(pp, bb);
        s_sp[tid] = sp;
    }
    if (tid == 0) s_scal = 2.0f * expf(-log_dt[d]);   // 2/dt
    __syncthreads();

    const int k1 = blockIdx.x * blockDim.x + tid;     // 0..4095
    const int k2 = k1 + HALF_L;                       // 4096..8191
    const float scal = s_scal;

    // per-point prologue (f32 angle as in the reference)
    const float w0 = (float)(-6.283185307179586476925286766559 / (double)SEQ_L);
    float zs1, zc1, zs2, zc2;
    sincosf(w0 * (float)k1, &zs1, &zc1);
    sincosf(w0 * (float)k2, &zs2, &zc2);

    float dzr1 = 1.0f + zc1, dzi1 = zs1;
    float dzr2 = 1.0f + zc2, dzi2 = zs2;
    if (k2 == HALF_L) { dzr2 = 1.1920929e-7f; dzi2 = 0.0f; }
    float idm1 = 1.0f / (dzr1 * dzr1 + dzi1 * dzi1);
    float idm2 = 1.0f / (dzr2 * dzr2 + dzi2 * dzi2);

    float nr1 = 1.0f - zc1, ni1 = -zs1;
    float nr2 = 1.0f - zc2, ni2 = -zs2;
    const float gi1  = scal * (ni1 * dzr1 - nr1 * dzi1) * idm1;
    const float gi2  = scal * (ni2 * dzr2 - nr2 * dzi2) * idm2;
    float pfr1 =  2.0f * dzr1 * idm1, pfi1 = -2.0f * dzi1 * idm1;
    float pfr2 =  2.0f * dzr2 * idm2, pfi2 = -2.0f * dzi2 * idm2;

    float SA1 = 0.f, SB1 = 0.f, SC1 = 0.f, SD1 = 0.f;
    float TA1 = 0.f, TB1 = 0.f, TC1 = 0.f, TD1 = 0.f;
    float SA2 = 0.f, SB2 = 0.f, SC2 = 0.f, SD2 = 0.f;
    float TA2 = 0.f, TB2 = 0.f, TC2 = 0.f, TD2 = 0.f;

#pragma unroll 8
    for (int n = 0; n < STATE_N; n++) {
        float4 a = s_p1[n];
        float4 b = s_p2[n];
        float2 c = s_p3[n];
        // point 1
        float di1 = gi1 - a.x;
        float m1  = fmaf(di1, di1, a.y);
        float i1; asm("rcp.approx.f32 %0, %1;" : "=f"(i1) : "f"(m1));
        float Ri1 = di1 * i1;
        SA1 = fmaf(b.x, i1, SA1);  SB1 = fmaf(b.y, i1, SB1);
        SC1 = fmaf(b.z, i1, SC1);  SD1 = fmaf(b.w, i1, SD1);
        TA1 = fmaf(a.z, Ri1, TA1); TB1 = fmaf(a.w, Ri1, TB1);
        TC1 = fmaf(c.x, Ri1, TC1); TD1 = fmaf(c.y, Ri1, TD1);
        // point 2
        float di2 = gi2 - a.x;
        float m2  = fmaf(di2, di2, a.y);
        float i2; asm("rcp.approx.f32 %0, %1;" : "=f"(i2) : "f"(m2));
        float Ri2 = di2 * i2;
        SA2 = fmaf(b.x, i2, SA2);  SB2 = fmaf(b.y, i2, SB2);
        SC2 = fmaf(b.z, i2, SC2);  SD2 = fmaf(b.w, i2, SD2);
        TA2 = fmaf(a.z, Ri2, TA2); TB2 = fmaf(a.w, Ri2, TB2);
        TC2 = fmaf(c.x, Ri2, TC2); TD2 = fmaf(c.y, Ri2, TD2);
    }

    // ---- finalize both points ----
    float2* dst = g_Khat + d * SEQ_L;
#pragma unroll
    for (int pt = 0; pt < 2; pt++) {
        float SA = pt ? SA2 : SA1, SB = pt ? SB2 : SB1;
        float SC = pt ? SC2 : SC1, SD = pt ? SD2 : SD1;
        float TA = pt ? TA2 : TA1, TB = pt ? TB2 : TB1;
        float TC = pt ? TC2 : TC1, TD = pt ? TD2 : TD1;
        float pfr = pt ? pfr2 : pfr1, pfi = pt ? pfi2 : pfi1;
        int   k   = pt ? k2 : k1;

        float PRBr, PRBi, BRPr, BRPi, PRPr, PRPi, BRBr, BRBi;
        if (k != HALF_L) {
            PRBr = SA + TB;  PRBi = SB - TA;
            BRPr = SA - TB;  BRPi = -SB - TA;
            PRPr = SC;       PRPi = -TC;
            BRBr = SD;       BRBi = -TD;
        } else {
            // exact general path for the eps-clamped point (g real part huge)
            float gi = gi2;
            float gr = scal * (nr2 * dzr2 + ni2 * dzi2) * idm2;
            PRBr = PRBi = BRPr = BRPi = PRPr = PRPi = BRBr = BRBi = 0.f;
            for (int n = 0; n < STATE_N; n++) {
                float4 a = s_p1[n];
                float2 c = s_p3[n];
                float dr = gr + s_sp[n];          // gr - lam_re
                float di = gi - a.x;
                float m  = fmaf(dr, dr, di * di);
                float inv = 1.0f / m;
                float Rtr = dr * inv;
                float Rti = -di * inv;
                float w1r = a.z, w1i = a.w, pp = c.x, bb = c.y;
                PRBr += w1r * Rtr - w1i * Rti;
                PRBi += w1r * Rti + w1i * Rtr;
                BRPr += w1r * Rtr + w1i * Rti;
                BRPi += w1r * Rti - w1i * Rtr;
                PRPr += pp * Rtr;  PRPi += pp * Rti;
                BRBr += bb * Rtr;  BRBi += bb * Rti;
            }
        }

        float qr = 1.0f + PRPr, qi = PRPi;
        float iq = 1.0f / (qr * qr + qi * qi);
        float numr = BRPr * PRBr - BRPi * PRBi;
        float numi = BRPr * PRBi + BRPi * PRBr;
        float tr = (numr * qr + numi * qi) * iq;
        float ti = (numi * qr - numr * qi) * iq;
        float hr = BRBr - tr;
        float hi = BRBi - ti;
        dst[k] = make_float2(pfr * hr - pfi * hi, pfr * hi + pfi * hr);
    }
}

// ---------------------------------------------------------------------------
// Kernel 2: Re(ifft_L(X)) = Hermitian fold + 4096-pt radix-4 inverse Stockham.
// One CTA per d-row, 64 KB smem ping-pong, 1024 threads.
// ---------------------------------------------------------------------------
__global__ void __launch_bounds__(1024) ifft_kernel(float* __restrict__ out)
{
    extern __shared__ float2 sm[];
    float2* x = sm;
    float2* y = sm + HALF_L;

    const int d   = blockIdx.x;
    const int tid = threadIdx.x;
    const int NT  = 1024;

    const float2* src = g_Khat + d * SEQ_L;

    // Hermitian fold + even/odd pack:  x[k] = E[k] + i*O[k]
    const float thL = 6.28318530717958647692f / (float)SEQ_L;
    for (int kk = tid; kk < HALF_L; kk += NT) {
        float2 Xa  = src[kk];
        float2 Xam = src[kk == 0 ? 0 : SEQ_L - kk];
        float2 Xb  = src[kk + HALF_L];
        float2 Xbm = src[HALF_L - kk];
        float Ar = 0.5f * (Xa.x + Xam.x), Ai = 0.5f * (Xa.y - Xam.y);
        float Br = 0.5f * (Xb.x + Xbm.x), Bi = 0.5f * (Xb.y - Xbm.y);
        float Er = 0.5f * (Ar + Br), Ei = 0.5f * (Ai + Bi);
        float Dr = 0.5f * (Ar - Br), Di = 0.5f * (Ai - Bi);
        float swr, swi;
        __sincosf(thL * (float)kk, &swi, &swr);
        float Or = Dr * swr - Di * swi;
        float Oi = Dr * swi + Di * swr;
        x[kk] = make_float2(Er - Oi, Ei + Or);
    }
    __syncthreads();

    int n = HALF_L, s = 1, ls = 0;
    while (n > 1) {
        const int m = n >> 2;
        const float th = 6.28318530717958647692f / (float)n;
        for (int u = tid; u < (HALF_L >> 2); u += NT) {
            int p = u >> ls;
            int q = u & (s - 1);
            int base = q + s * p;
            float2 a  = x[base];
            float2 b  = x[base + s * m];
            float2 c  = x[base + s * 2 * m];
            float2 dd = x[base + s * 3 * m];

            float w1i, w1r;
            __sincosf(th * (float)p, &w1i, &w1r);
            float w2r = w1r * w1r - w1i * w1i;
            float w2i = 2.0f * w1r * w1i;
            float w3r = w2r * w1r - w2i * w1i;
            float w3i = w2r * w1i + w2i * w1r;

            float acr = a.x + c.x, aci = a.y + c.y;
            float amr = a.x - c.x, ami = a.y - c.y;
            float bdr = b.x + dd.x, bdi = b.y + dd.y;
            float bmr = b.x - dd.x, bmi = b.y - dd.y;

            float X0r = acr + bdr, X0i = aci + bdi;
            float X2r = acr - bdr, X2i = aci - bdi;
            float X1r = amr - bmi, X1i = ami + bmr;
            float X3r = amr + bmi, X3i = ami - bmr;

            int ob = q + s * 4 * p;
            y[ob]         = make_float2(X0r, X0i);
            y[ob + s]     = make_float2(X1r * w1r - X1i * w1i,
                                        X1r * w1i + X1i * w1r);
            y[ob + 2 * s] = make_float2(X2r * w2r - X2i * w2i,
                                        X2r * w2i + X2i * w2r);
            y[ob + 3 * s] = make_float2(X3r * w3r - X3i * w3i,
                                        X3r * w3i + X3i * w3r);
        }
        __syncthreads();
        float2* tmp = x; x = y; y = tmp;
        n = m; s <<= 2; ls += 2;
    }

    const float scale = 1.0f / (float)HALF_L;
    float* dst = out + d * SEQ_L;
    for (int mI = tid; mI < HALF_L; mI += NT) {
        float2 v = x[mI];
        dst[2 * mI]     = v.x * scale;
        dst[2 * mI + 1] = v.y * scale;
    }
}

// ---------------------------------------------------------------------------
extern "C" void kernel_launch(void* const* d_in, const int* in_sizes, int n_in,
                              void* d_out, int out_size)
{
    const float* Lam_re = (const float*)d_in[0];
    const float* Lam_im = (const float*)d_in[1];
    const float* P_re   = (const float*)d_in[2];
    const float* P_im   = (const float*)d_in[3];
    const float* B_re   = (const float*)d_in[4];
    const float* B_im   = (const float*)d_in[5];
    const float* log_dt = (const float*)d_in[6];

    float* out = (float*)d_out;

    // Diagnostic no-ops: put cauchy_kernel in ncu's profiled slot (#4).
    dummy_a<<<1, 32>>>();
    dummy_b<<<1, 32>>>();
    dummy_c<<<1, 32>>>();

    // Stage 1: Cauchy + Woodbury -> K_hat (2 points per thread)
    dim3 gridA(HALF_L / 256, D_MODEL);   // 16 x 256
    cauchy_kernel<<<gridA, 256>>>(Lam_re, Lam_im, P_re, P_im, B_re, B_im, log_dt);

    // Stage 2: Hermitian fold + radix-4 half-length iFFT per row -> K
    cudaFuncSetAttribute(ifft_kernel,
                         cudaFuncAttributeMaxDynamicSharedMemorySize, 65536);
    ifft_kernel<<<D_MODEL, 1024, 65536>>>(out);

    // Tail of the output: D buffer (zeros in the reference)
    long kElems = (long)D_MODEL * SEQ_L;
    if ((long)out_size > kElems) {
        cudaMemsetAsync(out + kElems, 0,
                        ((long)out_size - kElems) * sizeof(float), 0);
    }
}

// round 9
// speedup vs baseline: 1.1211x; 1.0828x over previous
#include <cuda_runtime.h>
#include <math.h>

#define D_MODEL 256
#define STATE_N 64
#define SEQ_L   8192
#define HALF_L  4096
#define QUART_L 2048

// Scratch: packed half-spectrum x[d][HALF_L] complex64 (8 MB).
__device__ float2 g_Khat[D_MODEL * HALF_L];

// ---------------------------------------------------------------------------
// Woodbury tail from the 8 fast-path sums (g purely imaginary form).
// ---------------------------------------------------------------------------
__device__ __forceinline__ float2 wb_fast(float SA, float SB, float SC, float SD,
                                          float TA, float TB, float TC, float TD,
                                          float pfr, float pfi)
{
    float PRBr = SA + TB, PRBi = SB - TA;
    float BRPr = SA - TB, BRPi = -SB - TA;
    float qr = 1.0f + SC, qi = -TC;
    float BRBr = SD, BRBi = -TD;
    float iq = 1.0f / (qr * qr + qi * qi);
    float numr = BRPr * PRBr - BRPi * PRBi;
    float numi = BRPr * PRBi + BRPi * PRBr;
    float tr = (numr * qr + numi * qi) * iq;
    float ti = (numi * qr - numr * qi) * iq;
    float hr = BRBr - tr, hi = BRBi - ti;
    return make_float2(pfr * hr - pfi * hi, pfr * hi + pfi * hr);
}

// Hermitian fold + even/odd pack: packed x for index kk given
// XA=X[kk], XB=X[L-kk], XC=X[kk+L/2], XD=X[L/2-kk], tw = e^{+2pi i kk/L}.
__device__ __forceinline__ float2 fold4(float2 XA, float2 XB, float2 XC, float2 XD,
                                        float twr, float twi)
{
    float XH1r = 0.5f * (XA.x + XB.x), XH1i = 0.5f * (XA.y - XB.y);
    float XH2r = 0.5f * (XC.x + XD.x), XH2i = 0.5f * (XC.y - XD.y);
    float Er = 0.5f * (XH1r + XH2r), Ei = 0.5f * (XH1i + XH2i);
    float Dr = 0.5f * (XH1r - XH2r), Di = 0.5f * (XH1i - XH2i);
    float Or = Dr * twr - Di * twi;
    float Oi = Dr * twi + Di * twr;
    return make_float2(Er - Oi, Ei + Or);
}

// ---------------------------------------------------------------------------
// Kernel 1: Cauchy + Woodbury, QUAD points per thread {k, L-k, L/2+k, L/2-k},
// fused with the Hermitian fold -> writes packed half-spectrum directly.
// blockIdx.y = d; 8 blocks x 256 threads cover k = 0..2047 (k=0 special).
// ---------------------------------------------------------------------------
__global__ void __launch_bounds__(256) cauchy_kernel(
    const float* __restrict__ Lam_re, const float* __restrict__ Lam_im,
    const float* __restrict__ P_re,   const float* __restrict__ P_im,
    const float* __restrict__ B_re,   const float* __restrict__ B_im,
    const float* __restrict__ log_dt)
{
    __shared__ float4 s_p1[STATE_N];  // (lam_im, sp*sp, w1r, w1i)
    __shared__ float4 s_p2[STATE_N];  // (w1r*sp, w1i*sp, pp*sp, bb*sp)
    __shared__ float2 s_p3[STATE_N];  // (pp, bb)
    __shared__ float  s_sp[STATE_N];  // sp (cold: exact path only)
    __shared__ float  s_scal;

    const int d   = blockIdx.y;
    const int tid = threadIdx.x;

    if (tid < STATE_N) {
        const int idx = d * STATE_N + tid;
        float lr = Lam_re[idx];
        float li = Lam_im[idx];
        float sp = fmaxf(lr, 0.0f) + log1pf(expf(-fabsf(lr)));  // softplus
        float pr = P_re[idx], pi = P_im[idx];
        float br = B_re[idx], bi = B_im[idx];
        float w1r = pr * br + pi * bi;    // conj(P)*B
        float w1i = pr * bi - pi * br;
        float pp  = pr * pr + pi * pi;
        float bb  = br * br + bi * bi;
        s_p1[tid] = make_float4(li, sp * sp, w1r, w1i);
        s_p2[tid] = make_float4(w1r * sp, w1i * sp, pp * sp, bb * sp);
        s_p3[tid] = make_float2(pp, bb);
        s_sp[tid] = sp;
    }
    if (tid == 0) s_scal = 2.0f * expf(-log_dt[d]);   // 2/dt
    __syncthreads();

    const int k = blockIdx.x * blockDim.x + tid;      // 0..2047
    const float scal = s_scal;
    const float w0 = (float)(-6.283185307179586476925286766559 / (double)SEQ_L);

    // Quad prologue. Slots: A=k, B=L-k, C=L/2+k, D=L/2-k.
    float giA, giB, giC, giD;
    float pfAr, pfAi, pfBr, pfBi, pfCr, pfCi, pfDr, pfDi;
    float zc = 1.0f, zs = 0.0f;

    if (k != 0) {
        sincosf(w0 * (float)k, &zs, &zc);          // z = (zc, zs)
        float idmA = 1.0f / ((1.0f + zc) * (1.0f + zc) + zs * zs);
        float idmC = 1.0f / ((1.0f - zc) * (1.0f - zc) + zs * zs);
        giA = -2.0f * scal * zs * idmA;  giB = -giA;
        giC =  2.0f * scal * zs * idmC;  giD = -giC;
        pfAr = 2.0f * (1.0f + zc) * idmA;  pfAi = -2.0f * zs * idmA;
        pfBr = pfAr;                       pfBi = -pfAi;
        pfCr = 2.0f * (1.0f - zc) * idmC;  pfCi =  2.0f * zs * idmC;
        pfDr = pfCr;                       pfDi = -pfCi;
    } else {
        // special quad: slots A=point 0, B=point 2048, C=point 6144, D=dummy
        giA = 0.0f; pfAr = 1.0f; pfAi = 0.0f;
        float zsb, zcb;
        sincosf(w0 * 2048.0f, &zsb, &zcb);
        float idmb = 1.0f / ((1.0f + zcb) * (1.0f + zcb) + zsb * zsb);
        giB = -2.0f * scal * zsb * idmb;
        pfBr = 2.0f * (1.0f + zcb) * idmb;  pfBi = -2.0f * zsb * idmb;
        float zsc, zcc;
        sincosf(w0 * 6144.0f, &zsc, &zcc);
        float idmc = 1.0f / ((1.0f + zcc) * (1.0f + zcc) + zsc * zsc);
        giC = -2.0f * scal * zsc * idmc;
        pfCr = 2.0f * (1.0f + zcc) * idmc;  pfCi = -2.0f * zsc * idmc;
        giD = 0.0f; pfDr = 0.0f; pfDi = 0.0f;
    }

    // 8 sums per point x 4 points
    float SA1=0,SB1=0,SC1=0,SD1=0, TA1=0,TB1=0,TC1=0,TD1=0;
    float SA2=0,SB2=0,SC2=0,SD2=0, TA2=0,TB2=0,TC2=0,TD2=0;
    float SA3=0,SB3=0,SC3=0,SD3=0, TA3=0,TB3=0,TC3=0,TD3=0;
    float SA4=0,SB4=0,SC4=0,SD4=0, TA4=0,TB4=0,TC4=0,TD4=0;

#pragma unroll 4
    for (int n = 0; n < STATE_N; n++) {
        float4 a = s_p1[n];
        float4 b = s_p2[n];
        float2 c = s_p3[n];

        float di, m, inv, Ri;
        di = giA - a.x;  m = fmaf(di, di, a.y);
        asm("rcp.approx.f32 %0, %1;" : "=f"(inv) : "f"(m));
        Ri = di * inv;
        SA1 = fmaf(b.x, inv, SA1);  SB1 = fmaf(b.y, inv, SB1);
        SC1 = fmaf(b.z, inv, SC1);  SD1 = fmaf(b.w, inv, SD1);
        TA1 = fmaf(a.z, Ri, TA1);   TB1 = fmaf(a.w, Ri, TB1);
        TC1 = fmaf(c.x, Ri, TC1);   TD1 = fmaf(c.y, Ri, TD1);

        di = giB - a.x;  m = fmaf(di, di, a.y);
        asm("rcp.approx.f32 %0, %1;" : "=f"(inv) : "f"(m));
        Ri = di * inv;
        SA2 = fmaf(b.x, inv, SA2);  SB2 = fmaf(b.y, inv, SB2);
        SC2 = fmaf(b.z, inv, SC2);  SD2 = fmaf(b.w, inv, SD2);
        TA2 = fmaf(a.z, Ri, TA2);   TB2 = fmaf(a.w, Ri, TB2);
        TC2 = fmaf(c.x, Ri, TC2);   TD2 = fmaf(c.y, Ri, TD2);

        di = giC - a.x;  m = fmaf(di, di, a.y);
        asm("rcp.approx.f32 %0, %1;" : "=f"(inv) : "f"(m));
        Ri = di * inv;
        SA3 = fmaf(b.x, inv, SA3);  SB3 = fmaf(b.y, inv, SB3);
        SC3 = fmaf(b.z, inv, SC3);  SD3 = fmaf(b.w, inv, SD3);
        TA3 = fmaf(a.z, Ri, TA3);   TB3 = fmaf(a.w, Ri, TB3);
        TC3 = fmaf(c.x, Ri, TC3);   TD3 = fmaf(c.y, Ri, TD3);

        di = giD - a.x;  m = fmaf(di, di, a.y);
        asm("rcp.approx.f32 %0, %1;" : "=f"(inv) : "f"(m));
        Ri = di * inv;
        SA4 = fmaf(b.x, inv, SA4);  SB4 = fmaf(b.y, inv, SB4);
        SC4 = fmaf(b.z, inv, SC4);  SD4 = fmaf(b.w, inv, SD4);
        TA4 = fmaf(a.z, Ri, TA4);   TB4 = fmaf(a.w, Ri, TB4);
        TC4 = fmaf(c.x, Ri, TC4);   TD4 = fmaf(c.y, Ri, TD4);
    }

    float2 XA = wb_fast(SA1,SB1,SC1,SD1, TA1,TB1,TC1,TD1, pfAr, pfAi);
    float2 XB = wb_fast(SA2,SB2,SC2,SD2, TA2,TB2,TC2,TD2, pfBr, pfBi);
    float2 XC = wb_fast(SA3,SB3,SC3,SD3, TA3,TB3,TC3,TD3, pfCr, pfCi);
    float2 XD = wb_fast(SA4,SB4,SC4,SD4, TA4,TB4,TC4,TD4, pfDr, pfDi);

    float2* dst = g_Khat + d * HALF_L;

    if (k != 0) {
        dst[k]          = fold4(XA, XB, XC, XD,  zc, -zs);
        dst[HALF_L - k] = fold4(XD, XC, XB, XA, -zc, -zs);
    } else {
        // exact Woodbury for the eps-clamped point k = L/2 = 4096
        float zs4, zc4;
        sincosf(w0 * 4096.0f, &zs4, &zc4);
        float dzr = 1.0f + zc4, dzi = zs4;
        if (sqrtf(dzr * dzr + dzi * dzi) < 1.1920929e-7f) {
            dzr = 1.1920929e-7f; dzi = 0.0f;
        }
        float idm = 1.0f / (dzr * dzr + dzi * dzi);
        float nr = 1.0f - zc4, ni = -zs4;
        float gr = scal * (nr * dzr + ni * dzi) * idm;
        float gi = scal * (ni * dzr - nr * dzi) * idm;
        float pfr = 2.0f * dzr * idm, pfi = -2.0f * dzi * idm;

        float PRBr=0,PRBi=0,BRPr=0,BRPi=0,PRPr=0,PRPi=0,BRBr=0,BRBi=0;
        for (int n = 0; n < STATE_N; n++) {
            float4 a = s_p1[n];
            float2 c = s_p3[n];
            float dr = gr + s_sp[n];
            float di = gi - a.x;
            float m  = fmaf(dr, dr, di * di);
            float inv = 1.0f / m;
            float Rtr = dr * inv;
            float Rti = -di * inv;
            float w1r = a.z, w1i = a.w, pp = c.x, bb = c.y;
            PRBr += w1r * Rtr - w1i * Rti;
            PRBi += w1r * Rti + w1i * Rtr;
            BRPr += w1r * Rtr + w1i * Rti;
            BRPi += w1r * Rti - w1i * Rtr;
            PRPr += pp * Rtr;  PRPi += pp * Rti;
            BRBr += bb * Rtr;  BRBi += bb * Rti;
        }
        float qr = 1.0f + PRPr, qi = PRPi;
        float iq = 1.0f / (qr * qr + qi * qi);
        float numr = BRPr * PRBr - BRPi * PRBi;
        float numi = BRPr * PRBi + BRPi * PRBr;
        float tr = (numr * qr + numi * qi) * iq;
        float ti = (numi * qr - numr * qi) * iq;
        float2 X4096 = make_float2(pfr * (BRBr - tr) - pfi * (BRBi - ti),
                                   pfr * (BRBi - ti) + pfi * (BRBr - tr));

        // emit packed x[0] and x[2048]
        dst[0]       = fold4(XA, XA, X4096, X4096, 1.0f, 0.0f);
        dst[QUART_L] = fold4(XB, XC, XC, XB, 0.0f, 1.0f);
    }
}

// ---------------------------------------------------------------------------
// Profiling positioner (keeps cauchy in ncu's captured slot).
// ---------------------------------------------------------------------------
__global__ void dummy_a() {}

// ---------------------------------------------------------------------------
// Kernel 2: 4096-pt radix-4 inverse Stockham on the packed spectrum.
// First stage reads gmem directly; 5 more stages in 64 KB smem ping-pong.
// ---------------------------------------------------------------------------
__global__ void __launch_bounds__(1024) ifft_kernel(float* __restrict__ out)
{
    extern __shared__ float2 sm[];
    float2* x = sm;
    float2* y = sm + HALF_L;

    const int d   = blockIdx.x;
    const int tid = threadIdx.x;
    const int NT  = 1024;

    const float2* src = g_Khat + d * HALF_L;

    // ---- stage 1 (n=4096, s=1): read gmem, write smem ----
    {
        const float th = 6.28318530717958647692f / 4096.0f;
        int p = tid;                        // u = tid, q = 0
        float2 a  = src[p];
        float2 b  = src[p + 1024];
        float2 c  = src[p + 2048];
        float2 dd = src[p + 3072];

        float w1i, w1r;
        __sincosf(th * (float)p, &w1i, &w1r);
        float w2r = w1r * w1r - w1i * w1i;
        float w2i = 2.0f * w1r * w1i;
        float w3r = w2r * w1r - w2i * w1i;
        float w3i = w2r * w1i + w2i * w1r;

        float acr = a.x + c.x, aci = a.y + c.y;
        float amr = a.x - c.x, ami = a.y - c.y;
        float bdr = b.x + dd.x, bdi = b.y + dd.y;
        float bmr = b.x - dd.x, bmi = b.y - dd.y;

        float X0r = acr + bdr, X0i = aci + bdi;
        float X2r = acr - bdr, X2i = aci - bdi;
        float X1r = amr - bmi, X1i = ami + bmr;
        float X3r = amr + bmi, X3i = ami - bmr;

        int ob = 4 * p;
        x[ob]     = make_float2(X0r, X0i);
        x[ob + 1] = make_float2(X1r * w1r - X1i * w1i, X1r * w1i + X1i * w1r);
        x[ob + 2] = make_float2(X2r * w2r - X2i * w2i, X2r * w2i + X2i * w2r);
        x[ob + 3] = make_float2(X3r * w3r - X3i * w3i, X3r * w3i + X3i * w3r);
    }
    __syncthreads();

    // ---- stages 2..6 in smem ----
    int n = 1024, s = 4, ls = 2;
    while (n > 1) {
        const int m = n >> 2;
        const float th = 6.28318530717958647692f / (float)n;
        {
            int u = tid;                    // one butterfly per thread
            int p = u >> ls;
            int q = u & (s - 1);
            int base = q + s * p;
            float2 a  = x[base];
            float2 b  = x[base + s * m];
            float2 c  = x[base + s * 2 * m];
            float2 dd = x[base + s * 3 * m];

            float w1i, w1r;
            __sincosf(th * (float)p, &w1i, &w1r);
            float w2r = w1r * w1r - w1i * w1i;
            float w2i = 2.0f * w1r * w1i;
            float w3r = w2r * w1r - w2i * w1i;
            float w3i = w2r * w1i + w2i * w1r;

            float acr = a.x + c.x, aci = a.y + c.y;
            float amr = a.x - c.x, ami = a.y - c.y;
            float bdr = b.x + dd.x, bdi = b.y + dd.y;
            float bmr = b.x - dd.x, bmi = b.y - dd.y;

            float X0r = acr + bdr, X0i = aci + bdi;
            float X2r = acr - bdr, X2i = aci - bdi;
            float X1r = amr - bmi, X1i = ami + bmr;
            float X3r = amr + bmi, X3i = ami - bmr;

            int ob = q + s * 4 * p;
            y[ob]         = make_float2(X0r, X0i);
            y[ob + s]     = make_float2(X1r * w1r - X1i * w1i,
                                        X1r * w1i + X1i * w1r);
            y[ob + 2 * s] = make_float2(X2r * w2r - X2i * w2i,
                                        X2r * w2i + X2i * w2r);
            y[ob + 3 * s] = make_float2(X3r * w3r - X3i * w3i,
                                        X3r * w3i + X3i * w3r);
        }
        __syncthreads();
        float2* tmp = x; x = y; y = tmp;
        n = m; s <<= 2; ls += 2;
    }

    // x[m] = K[2m] + i*K[2m+1]  ->  interleaved real output
    const float scale = 1.0f / (float)HALF_L;
    float* dstp = out + d * SEQ_L;
    for (int mI = tid; mI < HALF_L; mI += NT) {
        float2 v = x[mI];
        dstp[2 * mI]     = v.x * scale;
        dstp[2 * mI + 1] = v.y * scale;
    }
}

// ---------------------------------------------------------------------------
extern "C" void kernel_launch(void* const* d_in, const int* in_sizes, int n_in,
                              void* d_out, int out_size)
{
    const float* Lam_re = (const float*)d_in[0];
    const float* Lam_im = (const float*)d_in[1];
    const float* P_re   = (const float*)d_in[2];
    const float* P_im   = (const float*)d_in[3];
    const float* B_re   = (const float*)d_in[4];
    const float* B_im   = (const float*)d_in[5];
    const float* log_dt = (const float*)d_in[6];

    float* out = (float*)d_out;

    // Stage 1: Cauchy + Woodbury + fused Hermitian fold (quad points/thread)
    dim3 gridA(QUART_L / 256, D_MODEL);   // 8 x 256
    cauchy_kernel<<<gridA, 256>>>(Lam_re, Lam_im, P_re, P_im, B_re, B_im, log_dt);

    // keep cauchy in the ncu capture slot
    dummy_a<<<1, 32>>>();

    // Stage 2: radix-4 half-length iFFT per row -> K
    cudaFuncSetAttribute(ifft_kernel,
                         cudaFuncAttributeMaxDynamicSharedMemorySize, 65536);
    ifft_kernel<<<D_MODEL, 1024, 65536>>>(out);

    // Tail of the output: D buffer (zeros in the reference)
    long kElems = (long)D_MODEL * SEQ_L;
    if ((long)out_size > kElems) {
        cudaMemsetAsync(out + kElems, 0,
                        ((long)out_size - kElems) * sizeof(float), 0);
    }
}